// round 9
// baseline (speedup 1.0000x reference)
#include <cuda_runtime.h>

#define NB 8
#define NA 65536
#define NG 32

// ---- pass1 config ----
#define AW   64                // anchors per warp
#define WPB  8                 // warps per block
#define ABLK (AW * WPB)        // 512 anchors per block
#define NCH  (NA / ABLK)       // 128 chunks per batch
#define NBLK_A (NCH * NB)      // 1024 blocks

// ---- pass2 config ----
#define TPB 256
#define TAC 2
#define CHC (TPB * TAC)        // 512
#define NCHC (NA / CHC)        // 128
#define NBLK_C (NCHC * NB)     // 1024

// Scratch (no allocations allowed)
__device__ float    g_pi[NB * NG * NCH];
__device__ float    g_pu[NB * NG * NCH];
__device__ unsigned g_px[NB * NG * NCH];
__device__ unsigned g_mask[NB * NA];
__device__ float    g_class;
__device__ float    g_coord[NB];
__device__ int      g_cnt[NB];
__device__ int      g_tick;
__device__ int      g_tickA[NB];

// LG = log2(lanes per gt-group); G = 32>>LG anchors per warp-pass.
template <int LG>
__device__ __forceinline__ void kA_impl(
    const float* __restrict__ anchors,   // [A,4] xyxy
    const float* __restrict__ gt,        // [B,G,4] xywh
    int n, int b, int chunk)
{
    constexpr int GSZ = 1 << LG;
    constexpr int G   = 32 >> LG;
    constexpr unsigned MG = (GSZ == 32) ? 0xffffffffu : ((1u << GSZ) - 1u);

    const int tid  = threadIdx.x;
    const int lane = tid & 31, warp = tid >> 5;
    const int gl   = lane & (GSZ - 1);   // this lane's gt
    const int grp  = lane >> LG;         // this lane's anchor slot within pass

    // per-lane gt constants
    float gx1, gy1, gx2, gy2, sg;
    {
        float4 q = ((const float4*)gt)[b * NG + gl];   // cx,cy,w,h
        float hx = q.z * 0.5f, hy = q.w * 0.5f;
        gx1 = q.x - hx; gy1 = q.y - hy;
        gx2 = q.x + hx; gy2 = q.y + hy;
        sg  = (gx2 - gx1) * (gy2 - gy1);
        if (gl >= n) {          // sentinel: zero overlap with any anchor
            gx1 = 3e9f; gx2 = 3e9f; gy1 = 0.f; gy2 = 1.f; sg = 0.f;
        }
    }

    const int wbase = chunk * ABLK + warp * AW;
    unsigned* __restrict__ mrow = &g_mask[b * NA];

    // 4 independent argmax accumulators — overlapping select chains
    float    bi[4], bu[4];
    unsigned bx[4];
#pragma unroll
    for (int k = 0; k < 4; k++) {
        bi[k] = 0.f; bu[k] = 1.f; bx[k] = (unsigned)(wbase + k * G + grp);
    }

#pragma unroll
    for (int it = 0; it < AW / (4 * G); it++) {
        const int a = wbase + it * 4 * G;
        unsigned bals[4];
#pragma unroll
        for (int k = 0; k < 4; k++) {
            const int ak = a + k * G + grp;
            float4 q = __ldg(((const float4*)anchors) + ak);
            float sa = (q.z - q.x) * (q.w - q.y);
            float lx = fmaxf(q.x, gx1), ly = fmaxf(q.y, gy1);
            float rx = fminf(q.z, gx2), ry = fminf(q.w, gy2);
            float w  = fmaxf(rx - lx, 0.f), h = fmaxf(ry - ly, 0.f);
            float inter = w * h;
            float u = (sa + sg) - inter;
            // exact sign of inter - 0.5u (single rounding; 0.5u exact)
            bals[k] = __ballot_sync(0xffffffffu, fmaf(-0.5f, u, inter) > 0.f);
            // iou > best  <=>  inter*bu > bi*u  (u,bu > 0); strict > keeps
            // earliest anchor in this slot's ascending sequence
            bool better = inter * bu[k] > bi[k] * u;
            bi[k] = better ? inter        : bi[k];
            bu[k] = better ? u            : bu[k];
            bx[k] = better ? (unsigned)ak : bx[k];
        }
        if (G == 1) {
            if (lane == 0)
                *(uint4*)&mrow[a] = make_uint4(bals[0], bals[1], bals[2], bals[3]);
        } else {
            if (gl == 0) {          // one lane per group stores its gsz-bit field
#pragma unroll
                for (int k = 0; k < 4; k++)
                    mrow[a + k * G + grp] = (bals[k] >> lane) & MG;
            }
        }
    }

    // merge 4 slots (disjoint anchor sets; explicit index tie-break)
    float Bi = bi[0], Bu = bu[0]; unsigned Bx = bx[0];
#pragma unroll
    for (int k = 1; k < 4; k++) {
        float A = bi[k] * Bu, C = Bi * bu[k];
        if (A > C || (A == C && bx[k] < Bx)) { Bi = bi[k]; Bu = bu[k]; Bx = bx[k]; }
    }

    __shared__ float    s_bi[WPB][32], s_bu[WPB][32];
    __shared__ unsigned s_bx[WPB][32];
    s_bi[warp][lane] = Bi; s_bu[warp][lane] = Bu; s_bx[warp][lane] = Bx;
    __syncthreads();

    if (tid < GSZ) {                // one thread per g: merge warps x groups
        float Ri = 0.f, Ru = 1.f; unsigned Rx = 0xffffffffu;
#pragma unroll
        for (int w = 0; w < WPB; w++)
#pragma unroll
            for (int j = 0; j < G; j++) {
                const int l = tid + (j << LG);
                float oi = s_bi[w][l], ou = s_bu[w][l];
                unsigned ox = s_bx[w][l];
                float A = oi * Ru, C = Ri * ou;
                if (A > C || (A == C && ox < Rx)) { Ri = oi; Ru = ou; Rx = ox; }
            }
        const int p = (b * NG + tid) * NCH + chunk;
        g_pi[p] = Ri; g_pu[p] = Ru; g_px[p] = Rx;
    }

    // per-batch ticket: last block of this batch finalizes (fused old kB)
    __shared__ bool s_last;
    __syncthreads();
    if (tid == 0) {
        __threadfence();
        s_last = (atomicAdd(&g_tickA[b], 1) == NCH - 1);
    }
    __syncthreads();
    if (!s_last) return;

    {
        const int g = tid >> 3, s = tid & 7;     // 8 threads per g
        const int base = (b * NG + g) * NCH;
        float Fi = 0.f, Fu = 1.f; unsigned Fx = 0xffffffffu;
#pragma unroll 4
        for (int c = s * (NCH / 8); c < (s + 1) * (NCH / 8); c++) {
            float oi = __ldcg(&g_pi[base + c]);
            float ou = __ldcg(&g_pu[base + c]);
            unsigned ox = __ldcg(&g_px[base + c]);
            float A = oi * Fu, C = Fi * ou;
            if (A > C || (A == C && ox < Fx)) { Fi = oi; Fu = ou; Fx = ox; }
        }
#pragma unroll
        for (int off = 4; off; off >>= 1) {
            float    oi = __shfl_down_sync(0xffffffffu, Fi, off, 8);
            float    ou = __shfl_down_sync(0xffffffffu, Fu, off, 8);
            unsigned ox = __shfl_down_sync(0xffffffffu, Fx, off, 8);
            float A = oi * Fu, C = Fi * ou;
            if (A > C || (A == C && ox < Fx)) { Fi = oi; Fu = ou; Fx = ox; }
        }
        if (s == 0 && g < n)
            atomicOr(&g_mask[b * NA + Fx], 1u << g);
        if (tid == 0) {
            g_coord[b] = 0.f; g_cnt[b] = 0; g_tickA[b] = 0;
            if (b == 0) { g_class = 0.f; g_tick = 0; }
        }
    }
}

__global__ __launch_bounds__(256) void kA16(
    const float* __restrict__ anchors, const float* __restrict__ gt,
    const int* __restrict__ nobj)
{
    const int b = blockIdx.x & (NB - 1), chunk = blockIdx.x >> 3;
    const int n = __ldg(nobj + b);
    if (n > 16) return;
    kA_impl<4>(anchors, gt, n, b, chunk);
}

__global__ __launch_bounds__(256) void kA32(
    const float* __restrict__ anchors, const float* __restrict__ gt,
    const int* __restrict__ nobj)
{
    const int b = blockIdx.x & (NB - 1), chunk = blockIdx.x >> 3;
    const int n = __ldg(nobj + b);
    if (n <= 16) return;
    kA_impl<5>(anchors, gt, n, b, chunk);
}

// -------- Pass 2: class + coord losses, ticketed finalize --------
__global__ __launch_bounds__(TPB) void kC(
    const float* __restrict__ boxes,   // [B,A,4]
    const float* __restrict__ cls,     // [B,A,2]
    const float* __restrict__ gt,      // [B,G,4]
    float* __restrict__ out)
{
    const int b    = blockIdx.y;
    const int base = blockIdx.x * CHC;
    const int tid  = threadIdx.x;
    const int lane = tid & 31, warp = tid >> 5;

    __shared__ float s_g[4][NG];
    if (tid < NG) {
        float4 q = ((const float4*)gt)[b * NG + tid];
        float hx = q.z * 0.5f, hy = q.w * 0.5f;
        s_g[0][tid] = q.x - hx; s_g[1][tid] = q.y - hy;
        s_g[2][tid] = q.x + hx; s_g[3][tid] = q.y + hy;
    }
    __syncthreads();

    const int a0 = base + tid * TAC;
    uint2  m2 = *(const uint2*)&g_mask[b * NA + a0];
    float4 c2 = ((const float4*)cls)[(b * NA + a0) >> 1];

    float p0 = m2.x ? c2.y : c2.x;
    float p1 = m2.y ? c2.w : c2.z;
    float o0 = 1.f - p0, o1 = 1.f - p1;
    float cls_sum = o0 * o0 * (-logf(p0)) + o1 * o1 * (-logf(p1));

    float crd_sum = 0.f; int cnt = 0;
#pragma unroll
    for (int k = 0; k < TAC; k++) {
        unsigned m = k ? m2.y : m2.x;
        if (m) {
            float4 q = ((const float4*)boxes)[b * NA + a0 + k];
            do {
                int g = __ffs(m) - 1; m &= m - 1;
                crd_sum += fabsf(q.x - s_g[0][g]) + fabsf(q.y - s_g[1][g])
                         + fabsf(q.z - s_g[2][g]) + fabsf(q.w - s_g[3][g]);
                cnt++;
            } while (m);
        }
    }
#pragma unroll
    for (int off = 16; off; off >>= 1) {
        cls_sum += __shfl_down_sync(0xffffffffu, cls_sum, off);
        crd_sum += __shfl_down_sync(0xffffffffu, crd_sum, off);
        cnt     += __shfl_down_sync(0xffffffffu, cnt, off);
    }
    __shared__ float r_cls[8], r_crd[8];
    __shared__ int   r_cnt[8];
    if (lane == 0) { r_cls[warp] = cls_sum; r_crd[warp] = crd_sum; r_cnt[warp] = cnt; }
    __syncthreads();
    if (tid == 0) {
        float tc = 0.f, tr = 0.f; int tn = 0;
#pragma unroll
        for (int w = 0; w < 8; w++) { tc += r_cls[w]; tr += r_crd[w]; tn += r_cnt[w]; }
        atomicAdd(&g_class, tc);
        atomicAdd(&g_coord[b], tr);
        atomicAdd(&g_cnt[b], tn);
        __threadfence();
        if (atomicAdd(&g_tick, 1) == NBLK_C - 1) {   // last block finalizes
            __threadfence();
            float coord = 0.f;
#pragma unroll
            for (int bb = 0; bb < NB; bb++) {
                float c  = *(volatile float*)&g_coord[bb];
                int   nn = *(volatile int*)&g_cnt[bb];
                coord += c / (4.f * (float)nn);
            }
            float cl = (*(volatile float*)&g_class) * (0.01f / 8.f);
            float co = coord * (1.0f / 8.f);
            out[0] = cl + co;
            out[1] = cl;
            out[2] = co;
        }
    }
}

extern "C" void kernel_launch(void* const* d_in, const int* in_sizes, int n_in,
                              void* d_out, int out_size) {
    const float* boxes   = (const float*)d_in[0];   // [8,65536,4]
    const float* classes = (const float*)d_in[1];   // [8,65536,2]
    const float* anchors = (const float*)d_in[2];   // [65536,4]
    const float* gt      = (const float*)d_in[3];   // [8,32,4]
    const int*   nobj    = (const int*)d_in[4];     // [8]
    float* out = (float*)d_out;

    kA16<<<NBLK_A, 256>>>(anchors, gt, nobj);
    kA32<<<NBLK_A, 256>>>(anchors, gt, nobj);
    kC<<<dim3(NCHC, NB), TPB>>>(boxes, classes, gt, out);
}

// round 10
// speedup vs baseline: 1.4298x; 1.4298x over previous
#include <cuda_runtime.h>

#define NB 8
#define NA 65536
#define NG 32

// ---- pass1 config ----
#define AW   64                // anchors per warp
#define WPB  8                 // warps per block
#define ABLK (AW * WPB)        // 512 anchors per block
#define NCH  (NA / ABLK)       // 128 chunks per batch
#define NBLK_A (NCH * NB)      // 1024 blocks

// ---- pass2 config ----
#define TPB 256
#define TAC 4
#define CHC (TPB * TAC)        // 1024
#define NCHC (NA / CHC)        // 64
#define NBLK_C (NCHC * NB)     // 512

// Scratch (no allocations allowed)
__device__ float    g_pi[NB * NG * NCH];
__device__ float    g_pu[NB * NG * NCH];
__device__ unsigned g_px[NB * NG * NCH];
__device__ unsigned g_mask[NB * NA];
__device__ float    g_class;
__device__ float    g_coord[NB];
__device__ int      g_cnt[NB];
__device__ int      g_tick;
__device__ int      g_tickA[NB];

// LG = log2(lanes per gt-group); G = 32>>LG anchors per slot-pass. 2 slots.
template <int LG>
__device__ __forceinline__ void kA_impl(
    const float* __restrict__ anchors,   // [A,4] xyxy
    const float* __restrict__ gt,        // [B,G,4] xywh
    int n, int b, int chunk)
{
    constexpr int GSZ = 1 << LG;
    constexpr int G   = 32 >> LG;
    constexpr unsigned MG = (GSZ == 32) ? 0xffffffffu : ((1u << GSZ) - 1u);

    const int tid  = threadIdx.x;
    const int lane = tid & 31, warp = tid >> 5;
    const int gl   = lane & (GSZ - 1);   // this lane's gt
    const int grp  = lane >> LG;         // this lane's anchor slot within pass

    // per-lane gt constants
    float gx1, gy1, gx2, gy2, sg;
    {
        float4 q = ((const float4*)gt)[b * NG + gl];   // cx,cy,w,h
        float hx = q.z * 0.5f, hy = q.w * 0.5f;
        gx1 = q.x - hx; gy1 = q.y - hy;
        gx2 = q.x + hx; gy2 = q.y + hy;
        sg  = (gx2 - gx1) * (gy2 - gy1);
        if (gl >= n) {          // sentinel: zero overlap with any anchor
            gx1 = 3e9f; gx2 = 3e9f; gy1 = 0.f; gy2 = 1.f; sg = 0.f;
        }
    }

    const int wbase = chunk * ABLK + warp * AW;
    unsigned* __restrict__ mrow = &g_mask[b * NA];

    // 2 independent argmax accumulators — overlapping select chains
    float    bi0 = 0.f, bu0 = 1.f, bi1 = 0.f, bu1 = 1.f;
    unsigned bx0 = (unsigned)(wbase + grp);
    unsigned bx1 = (unsigned)(wbase + G + grp);

#pragma unroll
    for (int it = 0; it < AW / (2 * G); it++) {
        const int a = wbase + it * 2 * G;
        unsigned bal0, bal1;
#pragma unroll
        for (int k = 0; k < 2; k++) {
            const int ak = a + k * G + grp;
            float4 q = __ldg(((const float4*)anchors) + ak);
            float sa = (q.z - q.x) * (q.w - q.y);
            float lx = fmaxf(q.x, gx1), ly = fmaxf(q.y, gy1);
            float rx = fminf(q.z, gx2), ry = fminf(q.w, gy2);
            float w  = fmaxf(rx - lx, 0.f), h = fmaxf(ry - ly, 0.f);
            float inter = w * h;
            float u = (sa + sg) - inter;
            // exact sign of inter - 0.5u (single rounding; 0.5u exact)
            unsigned bal = __ballot_sync(0xffffffffu, fmaf(-0.5f, u, inter) > 0.f);
            // iou > best  <=>  inter*bu > bi*u  (u,bu > 0); strict > keeps
            // earliest anchor in this slot's ascending sequence
            if (k == 0) {
                bal0 = bal;
                bool better = inter * bu0 > bi0 * u;
                bi0 = better ? inter : bi0;
                bu0 = better ? u     : bu0;
                bx0 = better ? (unsigned)ak : bx0;
            } else {
                bal1 = bal;
                bool better = inter * bu1 > bi1 * u;
                bi1 = better ? inter : bi1;
                bu1 = better ? u     : bu1;
                bx1 = better ? (unsigned)ak : bx1;
            }
        }
        if (G == 1) {
            if (lane == 0)
                *(uint2*)&mrow[a] = make_uint2(bal0, bal1);
        } else {
            if (gl == 0) {      // one lane per group stores its gsz-bit field
                mrow[a + grp]     = (bal0 >> lane) & MG;
                mrow[a + G + grp] = (bal1 >> lane) & MG;
            }
        }
    }

    // merge 2 slots (disjoint anchor sets; explicit index tie-break)
    float Bi = bi0, Bu = bu0; unsigned Bx = bx0;
    {
        float A = bi1 * Bu, C = Bi * bu1;
        if (A > C || (A == C && bx1 < Bx)) { Bi = bi1; Bu = bu1; Bx = bx1; }
    }

    __shared__ float    s_bi[WPB][32], s_bu[WPB][32];
    __shared__ unsigned s_bx[WPB][32];
    s_bi[warp][lane] = Bi; s_bu[warp][lane] = Bu; s_bx[warp][lane] = Bx;
    __syncthreads();

    if (tid < GSZ) {                // one thread per g: merge warps x groups
        float Ri = 0.f, Ru = 1.f; unsigned Rx = 0xffffffffu;
#pragma unroll
        for (int w = 0; w < WPB; w++)
#pragma unroll
            for (int j = 0; j < G; j++) {
                const int l = tid + (j << LG);
                float oi = s_bi[w][l], ou = s_bu[w][l];
                unsigned ox = s_bx[w][l];
                float A = oi * Ru, C = Ri * ou;
                if (A > C || (A == C && ox < Rx)) { Ri = oi; Ru = ou; Rx = ox; }
            }
        const int p = (b * NG + tid) * NCH + chunk;
        g_pi[p] = Ri; g_pu[p] = Ru; g_px[p] = Rx;
    }

    // per-batch ticket: last block of this batch finalizes (fused kB)
    __shared__ bool s_last;
    __syncthreads();
    if (tid == 0) {
        __threadfence();
        s_last = (atomicAdd(&g_tickA[b], 1) == NCH - 1);
    }
    __syncthreads();
    if (!s_last) return;

    {
        const int g = tid >> 3, s = tid & 7;     // 8 threads per g
        const int base = (b * NG + g) * NCH;
        float Fi = 0.f, Fu = 1.f; unsigned Fx = 0xffffffffu;
#pragma unroll 4
        for (int c = s * (NCH / 8); c < (s + 1) * (NCH / 8); c++) {
            float oi = __ldcg(&g_pi[base + c]);
            float ou = __ldcg(&g_pu[base + c]);
            unsigned ox = __ldcg(&g_px[base + c]);
            float A = oi * Fu, C = Fi * ou;
            if (A > C || (A == C && ox < Fx)) { Fi = oi; Fu = ou; Fx = ox; }
        }
#pragma unroll
        for (int off = 4; off; off >>= 1) {
            float    oi = __shfl_down_sync(0xffffffffu, Fi, off, 8);
            float    ou = __shfl_down_sync(0xffffffffu, Fu, off, 8);
            unsigned ox = __shfl_down_sync(0xffffffffu, Fx, off, 8);
            float A = oi * Fu, C = Fi * ou;
            if (A > C || (A == C && ox < Fx)) { Fi = oi; Fu = ou; Fx = ox; }
        }
        if (s == 0 && g < n)
            atomicOr(&g_mask[b * NA + Fx], 1u << g);
        if (tid == 0) {
            g_coord[b] = 0.f; g_cnt[b] = 0; g_tickA[b] = 0;
            if (b == 0) { g_class = 0.f; g_tick = 0; }
        }
    }
}

__global__ __launch_bounds__(256) void kA(
    const float* __restrict__ anchors, const float* __restrict__ gt,
    const int* __restrict__ nobj)
{
    const int b = blockIdx.x & (NB - 1), chunk = blockIdx.x >> 3;
    const int n = __ldg(nobj + b);
    if (n <= 16)
        kA_impl<4>(anchors, gt, n, b, chunk);
    else
        kA_impl<5>(anchors, gt, n, b, chunk);
}

// -------- Pass 2: class + coord losses, ticketed finalize --------
__global__ __launch_bounds__(TPB) void kC(
    const float* __restrict__ boxes,   // [B,A,4]
    const float* __restrict__ cls,     // [B,A,2]
    const float* __restrict__ gt,      // [B,G,4]
    float* __restrict__ out)
{
    const int b    = blockIdx.y;
    const int base = blockIdx.x * CHC;
    const int tid  = threadIdx.x;
    const int lane = tid & 31, warp = tid >> 5;

    __shared__ float s_g[4][NG];
    if (tid < NG) {
        float4 q = ((const float4*)gt)[b * NG + tid];
        float hx = q.z * 0.5f, hy = q.w * 0.5f;
        s_g[0][tid] = q.x - hx; s_g[1][tid] = q.y - hy;
        s_g[2][tid] = q.x + hx; s_g[3][tid] = q.y + hy;
    }
    __syncthreads();

    const int a0 = base + tid * TAC;
    // all loads issued up front (MLP)
    uint4  m4  = *(const uint4*)&g_mask[b * NA + a0];
    float4 c01 = ((const float4*)cls)[(b * NA + a0) >> 1];
    float4 c23 = ((const float4*)cls)[((b * NA + a0) >> 1) + 1];

    float p0 = m4.x ? c01.y : c01.x;
    float p1 = m4.y ? c01.w : c01.z;
    float p2 = m4.z ? c23.y : c23.x;
    float p3 = m4.w ? c23.w : c23.z;
    float o0 = 1.f - p0, o1 = 1.f - p1, o2 = 1.f - p2, o3 = 1.f - p3;
    float cls_sum = o0 * o0 * (-__logf(p0)) + o1 * o1 * (-__logf(p1))
                  + o2 * o2 * (-__logf(p2)) + o3 * o3 * (-__logf(p3));

    float crd_sum = 0.f; int cnt = 0;
#pragma unroll
    for (int k = 0; k < TAC; k++) {
        unsigned m = (k == 0) ? m4.x : (k == 1) ? m4.y : (k == 2) ? m4.z : m4.w;
        if (m) {
            float4 q = ((const float4*)boxes)[b * NA + a0 + k];
            do {
                int g = __ffs(m) - 1; m &= m - 1;
                crd_sum += fabsf(q.x - s_g[0][g]) + fabsf(q.y - s_g[1][g])
                         + fabsf(q.z - s_g[2][g]) + fabsf(q.w - s_g[3][g]);
                cnt++;
            } while (m);
        }
    }
#pragma unroll
    for (int off = 16; off; off >>= 1) {
        cls_sum += __shfl_down_sync(0xffffffffu, cls_sum, off);
        crd_sum += __shfl_down_sync(0xffffffffu, crd_sum, off);
        cnt     += __shfl_down_sync(0xffffffffu, cnt, off);
    }
    __shared__ float r_cls[8], r_crd[8];
    __shared__ int   r_cnt[8];
    if (lane == 0) { r_cls[warp] = cls_sum; r_crd[warp] = crd_sum; r_cnt[warp] = cnt; }
    __syncthreads();
    if (tid == 0) {
        float tc = 0.f, tr = 0.f; int tn = 0;
#pragma unroll
        for (int w = 0; w < 8; w++) { tc += r_cls[w]; tr += r_crd[w]; tn += r_cnt[w]; }
        atomicAdd(&g_class, tc);
        atomicAdd(&g_coord[b], tr);
        atomicAdd(&g_cnt[b], tn);
        __threadfence();
        if (atomicAdd(&g_tick, 1) == NBLK_C - 1) {   // last block finalizes
            __threadfence();
            float coord = 0.f;
#pragma unroll
            for (int bb = 0; bb < NB; bb++) {
                float c  = *(volatile float*)&g_coord[bb];
                int   nn = *(volatile int*)&g_cnt[bb];
                coord += c / (4.f * (float)nn);
            }
            float cl = (*(volatile float*)&g_class) * (0.01f / 8.f);
            float co = coord * (1.0f / 8.f);
            out[0] = cl + co;
            out[1] = cl;
            out[2] = co;
        }
    }
}

extern "C" void kernel_launch(void* const* d_in, const int* in_sizes, int n_in,
                              void* d_out, int out_size) {
    const float* boxes   = (const float*)d_in[0];   // [8,65536,4]
    const float* classes = (const float*)d_in[1];   // [8,65536,2]
    const float* anchors = (const float*)d_in[2];   // [65536,4]
    const float* gt      = (const float*)d_in[3];   // [8,32,4]
    const int*   nobj    = (const int*)d_in[4];     // [8]
    float* out = (float*)d_out;

    kA<<<NBLK_A, 256>>>(anchors, gt, nobj);
    kC<<<dim3(NCHC, NB), TPB>>>(boxes, classes, gt, out);
}